// round 6
// baseline (speedup 1.0000x reference)
#include <cuda_runtime.h>
#include <math_constants.h>

#define WIN    400
#define RNUM   64
#define BNUM   2
#define ANUM   3
#define KSEL   8
#define W_TOT  1000
#define CHW    8                  // windows per chunk
#define RPC    16                 // ref rows per CTA
#define NCHUNK (W_TOT / CHW)      // 125
#define RBLK   (RNUM / RPC)       // 4
#define SPAN   (WIN * CHW)        // 3200 floats
#define NV4S   (SPAN / 4)         // 800 vec4
#define PV4    (2 * WIN / 4)      // 200 vec4 per window pair

// Scratch: scores [B, A, W, R] = 2*3*1000*64 floats = 1.5 MB (L2-resident).
__device__ float g_scores[BNUM * ANUM * W_TOT * RNUM];

// ---------------- Phase 1: windowed dot products ----------------
__global__ __launch_bounds__(256, 6) void phase1_kernel(
    const float* __restrict__ mixed,   // [B, S]
    const float* __restrict__ ref,     // [A, R, S]
    int S)
{
    const int chunk = blockIdx.x;      // 0..124
    const int rb    = blockIdx.y;      // 0..3
    const int a     = blockIdx.z;      // 0..2
    const int tid   = threadIdx.x;
    const int warp  = tid >> 5;
    const int lane  = tid & 31;

    __shared__ __align__(16) float sm_mixed[BNUM][SPAN];

    const long base = (long)chunk * SPAN;

    // Stage mixed chunk (both batch rows, 8 windows) into shared.
    {
        const float4* m4 = (const float4*)mixed;     // S % 4 == 0
        float4* sm4 = (float4*)&sm_mixed[0][0];
        for (int i = tid; i < BNUM * NV4S; i += 256) {
            int b = i / NV4S, v = i % NV4S;
            sm4[i] = m4[((long)b * S + base) / 4 + v];
        }
    }
    __syncthreads();

    const float4* sm0 = (const float4*)&sm_mixed[0][0];
    const float4* sm1 = (const float4*)&sm_mixed[1][0];

    // Each warp streams 2 ref rows, 12.8 KB contiguous per row.
    #pragma unroll
    for (int rr = 0; rr < 2; rr++) {
        const int r = rb * RPC + warp * 2 + rr;
        const float4* row4 = (const float4*)(ref + ((long)a * RNUM + r) * S + base);

        #pragma unroll
        for (int p = 0; p < CHW / 2; p++) {          // window pairs
            float s00 = 0.f, s01 = 0.f;   // batch0: win0, win1
            float s10 = 0.f, s11 = 0.f;   // batch1: win0, win1

            #pragma unroll
            for (int j = 0; j < 6; j++) {            // 192 vec4 full-warp
                const int l = j * 32 + lane;         // local in pair: 0..191
                const int v = p * PV4 + l;
                float4 rv = __ldg(&row4[v]);
                float4 m0 = sm0[v];
                float4 m1 = sm1[v];
                float c0 = rv.x * m0.x;
                c0 = fmaf(rv.y, m0.y, c0);
                c0 = fmaf(rv.z, m0.z, c0);
                c0 = fmaf(rv.w, m0.w, c0);
                float c1 = rv.x * m1.x;
                c1 = fmaf(rv.y, m1.y, c1);
                c1 = fmaf(rv.z, m1.z, c1);
                c1 = fmaf(rv.w, m1.w, c1);
                if (l < WIN / 4) { s00 += c0; s10 += c1; }
                else             { s01 += c0; s11 += c1; }
            }
            if (lane < PV4 - 192) {                  // tail: local 192..199, win1
                const int v = p * PV4 + 192 + lane;
                float4 rv = __ldg(&row4[v]);
                float4 m0 = sm0[v];
                float4 m1 = sm1[v];
                float c0 = rv.x * m0.x;
                c0 = fmaf(rv.y, m0.y, c0);
                c0 = fmaf(rv.z, m0.z, c0);
                c0 = fmaf(rv.w, m0.w, c0);
                float c1 = rv.x * m1.x;
                c1 = fmaf(rv.y, m1.y, c1);
                c1 = fmaf(rv.z, m1.z, c1);
                c1 = fmaf(rv.w, m1.w, c1);
                s01 += c0; s11 += c1;
            }
            // Warp reductions (4 values)
            #pragma unroll
            for (int off = 16; off > 0; off >>= 1) {
                s00 += __shfl_down_sync(0xffffffffu, s00, off);
                s01 += __shfl_down_sync(0xffffffffu, s01, off);
                s10 += __shfl_down_sync(0xffffffffu, s10, off);
                s11 += __shfl_down_sync(0xffffffffu, s11, off);
            }
            if (lane == 0) {
                const int wglob = chunk * CHW + p * 2;
                const long g0 = ((long)(0 * ANUM + a) * W_TOT + wglob);
                const long g1 = ((long)(1 * ANUM + a) * W_TOT + wglob);
                g_scores[g0 * RNUM + r]       = s00 * (1.0f / WIN);
                g_scores[(g0 + 1) * RNUM + r] = s01 * (1.0f / WIN);
                g_scores[g1 * RNUM + r]       = s10 * (1.0f / WIN);
                g_scores[(g1 + 1) * RNUM + r] = s11 * (1.0f / WIN);
            }
        }
    }
}

// ---------------- Phase 2: top-k + weighted pool ----------------
__global__ __launch_bounds__(256) void phase2_kernel(
    const float* __restrict__ weights,
    float* __restrict__ out,           // [6*W] scores ++ [6*W*K] idx (as float)
    int write_idx)
{
    const int tid  = threadIdx.x;
    const int warp = tid >> 5;
    const int lane = tid & 31;

    __shared__ float sm_w[KSEL];
    if (tid < KSEL) sm_w[tid] = weights[tid];
    __syncthreads();

    const int g = blockIdx.x * 8 + warp;            // (b*A + a)*W + w, < 6000

    float v0 = g_scores[(long)g * RNUM + lane];
    float v1 = g_scores[(long)g * RNUM + 32 + lane];
    float acc = 0.f;

    const long ibase = (long)BNUM * ANUM * W_TOT + (long)g * KSEL;

    #pragma unroll
    for (int k = 0; k < KSEL; k++) {
        float bv; int bi;
        if (v0 >= v1) { bv = v0; bi = lane; }        // ties -> lower index
        else          { bv = v1; bi = lane + 32; }
        #pragma unroll
        for (int off = 16; off > 0; off >>= 1) {
            float ov = __shfl_xor_sync(0xffffffffu, bv, off);
            int   oi = __shfl_xor_sync(0xffffffffu, bi, off);
            if (ov > bv || (ov == bv && oi < bi)) { bv = ov; bi = oi; }
        }
        acc = fmaf(bv, sm_w[k], acc);
        if (write_idx && lane == 0) out[ibase + k] = (float)bi;
        if (bi == lane)      v0 = -CUDART_INF_F;
        if (bi == lane + 32) v1 = -CUDART_INF_F;
    }
    if (lane == 0) out[g] = acc;
}

extern "C" void kernel_launch(void* const* d_in, const int* in_sizes, int n_in,
                              void* d_out, int out_size) {
    const float* mixed   = (const float*)d_in[0];
    const float* ref     = (const float*)d_in[1];
    const float* weights = (const float*)d_in[2];
    float* out = (float*)d_out;

    const int S = in_sizes[0] / BNUM;      // 400000
    const int W = S / WIN;                 // 1000 (== W_TOT)
    const int write_idx = (out_size >= BNUM * ANUM * W * (1 + KSEL)) ? 1 : 0;

    dim3 g1(NCHUNK, RBLK, ANUM);           // (125, 4, 3) = 1500 CTAs
    phase1_kernel<<<g1, 256>>>(mixed, ref, S);

    dim3 g2((BNUM * ANUM * W_TOT) / 8);    // 750 CTAs, warp per group
    phase2_kernel<<<g2, 256>>>(weights, out, write_idx);
}

// round 7
// speedup vs baseline: 3.4447x; 3.4447x over previous
#include <cuda_runtime.h>
#include <math_constants.h>

#define WIN    400
#define RNUM   64
#define BNUM   2
#define ANUM   3
#define KSEL   8
#define WPC    4                  // windows per CTA
#define SPAN   (WIN * WPC)        // 1600 floats
#define NV4S   (SPAN / 4)         // 400 vec4 per row span
#define PV4    (2 * WIN / 4)      // 200 vec4 per window pair
#define NTHR   512
#define NWARP  (NTHR / 32)        // 16
#define RPW    (RNUM / NWARP)     // 4 rows per warp

__global__ __launch_bounds__(NTHR) void win_topk_kernel(
    const float* __restrict__ mixed,    // [B, S]
    const float* __restrict__ ref,      // [A, R, S]
    const float* __restrict__ weights,  // [K]
    float* __restrict__ out,            // [6*W] scores ++ [6*W*K] idx (as float)
    int S, int W, int write_idx)
{
    const int wg   = blockIdx.x;        // window-group (4 windows)
    const int a    = blockIdx.y;
    const int tid  = threadIdx.x;
    const int warp = tid >> 5;
    const int lane = tid & 31;

    __shared__ __align__(16) float sm_mixed[BNUM][SPAN];
    __shared__ float sm_scores[BNUM][WPC][RNUM];
    __shared__ float sm_w[KSEL];

    const long base = (long)wg * SPAN;

    // Stage mixed span (both batch rows) into shared, vectorized.
    {
        const float4* m4 = (const float4*)mixed;  // S % 4 == 0, base % 4 == 0
        float4* sm4 = (float4*)&sm_mixed[0][0];
        for (int i = tid; i < BNUM * NV4S; i += NTHR) {   // 800 vec4
            int b = i / NV4S, v = i % NV4S;
            sm4[i] = m4[((long)b * S + base) / 4 + v];
        }
        if (tid < KSEL) sm_w[tid] = weights[tid];
    }
    __syncthreads();

    const float4* sm0 = (const float4*)&sm_mixed[0][0];
    const float4* sm1 = (const float4*)&sm_mixed[1][0];
    const float* refa = ref + ((long)a * RNUM) * S + base;

    // Each warp streams 4 ref rows; 6.4 KB contiguous per row.
    #pragma unroll 1
    for (int rr = 0; rr < RPW; rr++) {
        const int r = warp * RPW + rr;
        const float4* row4 = (const float4*)(refa + (long)r * S);

        #pragma unroll 1
        for (int p = 0; p < WPC / 2; p++) {       // window pairs
            float s00 = 0.f, s01 = 0.f;   // batch0: winA, winB
            float s10 = 0.f, s11 = 0.f;   // batch1: winA, winB

            #pragma unroll
            for (int j = 0; j < 6; j++) {          // 192 vec4 full-warp
                const int l = j * 32 + lane;       // local in pair: 0..191
                const int v = p * PV4 + l;
                float4 rv = __ldcs(&row4[v]);
                float4 m0 = sm0[v];
                float4 m1 = sm1[v];
                float c0 = rv.x * m0.x;
                c0 = fmaf(rv.y, m0.y, c0);
                c0 = fmaf(rv.z, m0.z, c0);
                c0 = fmaf(rv.w, m0.w, c0);
                float c1 = rv.x * m1.x;
                c1 = fmaf(rv.y, m1.y, c1);
                c1 = fmaf(rv.z, m1.z, c1);
                c1 = fmaf(rv.w, m1.w, c1);
                if (l < WIN / 4) { s00 += c0; s10 += c1; }
                else             { s01 += c0; s11 += c1; }
            }
            if (lane < PV4 - 192) {                // tail: local 192..199, winB
                const int v = p * PV4 + 192 + lane;
                float4 rv = __ldcs(&row4[v]);
                float4 m0 = sm0[v];
                float4 m1 = sm1[v];
                float c0 = rv.x * m0.x;
                c0 = fmaf(rv.y, m0.y, c0);
                c0 = fmaf(rv.z, m0.z, c0);
                c0 = fmaf(rv.w, m0.w, c0);
                float c1 = rv.x * m1.x;
                c1 = fmaf(rv.y, m1.y, c1);
                c1 = fmaf(rv.z, m1.z, c1);
                c1 = fmaf(rv.w, m1.w, c1);
                s01 += c0; s11 += c1;
            }
            // Warp reductions (4 values)
            #pragma unroll
            for (int off = 16; off > 0; off >>= 1) {
                s00 += __shfl_down_sync(0xffffffffu, s00, off);
                s01 += __shfl_down_sync(0xffffffffu, s01, off);
                s10 += __shfl_down_sync(0xffffffffu, s10, off);
                s11 += __shfl_down_sync(0xffffffffu, s11, off);
            }
            if (lane == 0) {
                sm_scores[0][p * 2 + 0][r] = s00 * (1.0f / WIN);
                sm_scores[0][p * 2 + 1][r] = s01 * (1.0f / WIN);
                sm_scores[1][p * 2 + 0][r] = s10 * (1.0f / WIN);
                sm_scores[1][p * 2 + 1][r] = s11 * (1.0f / WIN);
            }
        }
    }
    __syncthreads();

    // Top-K (K=8) over 64 refs; warps 0..7 handle the 8 (b, win) combos.
    if (warp < BNUM * WPC) {
        const int b   = warp >> 2;
        const int win = warp & 3;
        float v0 = sm_scores[b][win][lane];
        float v1 = sm_scores[b][win][lane + 32];
        float acc = 0.f;

        const int  wglob = wg * WPC + win;
        const long ow    = ((long)b * ANUM + a) * W + wglob;
        const long ibase = (long)BNUM * ANUM * W + ow * KSEL;

        #pragma unroll
        for (int k = 0; k < KSEL; k++) {
            float bv; int bi;
            if (v0 >= v1) { bv = v0; bi = lane; }        // ties -> lower index
            else          { bv = v1; bi = lane + 32; }
            #pragma unroll
            for (int off = 16; off > 0; off >>= 1) {
                float ov = __shfl_xor_sync(0xffffffffu, bv, off);
                int   oi = __shfl_xor_sync(0xffffffffu, bi, off);
                if (ov > bv || (ov == bv && oi < bi)) { bv = ov; bi = oi; }
            }
            acc = fmaf(bv, sm_w[k], acc);
            if (write_idx && lane == 0) out[ibase + k] = (float)bi;
            if (bi == lane)      v0 = -CUDART_INF_F;
            if (bi == lane + 32) v1 = -CUDART_INF_F;
        }
        if (lane == 0) out[ow] = acc;
    }
}

extern "C" void kernel_launch(void* const* d_in, const int* in_sizes, int n_in,
                              void* d_out, int out_size) {
    const float* mixed   = (const float*)d_in[0];
    const float* ref     = (const float*)d_in[1];
    const float* weights = (const float*)d_in[2];
    float* out = (float*)d_out;

    const int S = in_sizes[0] / BNUM;      // 400000
    const int W = S / WIN;                 // 1000
    const int write_idx = (out_size >= BNUM * ANUM * W * (1 + KSEL)) ? 1 : 0;

    dim3 grid(W / WPC, ANUM);              // (250, 3) = 750 CTAs x 512 thr
    win_topk_kernel<<<grid, NTHR>>>(mixed, ref, weights, out, S, W, write_idx);
}

// round 8
// speedup vs baseline: 3.6856x; 1.0699x over previous
#include <cuda_runtime.h>
#include <math_constants.h>

#define WIN    400
#define RNUM   64
#define BNUM   2
#define ANUM   3
#define KSEL   8
#define WPC    2                  // windows per CTA
#define SPAN   (WIN * WPC)        // 800 floats
#define NV4S   (SPAN / 4)         // 200 vec4 per row span
#define NTHR   256
#define NWARP  (NTHR / 32)        // 8
#define RPW    (RNUM / NWARP)     // 8 rows per warp
#define DYN_BYTES ((NWARP * 2 * NV4S + BNUM * NV4S) * 16)   // 57600

__device__ __forceinline__ void cpa16(float4* dst, const float4* src) {
    unsigned d = (unsigned)__cvta_generic_to_shared(dst);
    asm volatile("cp.async.cg.shared.global [%0], [%1], 16;\n" :: "r"(d), "l"(src));
}

__global__ __launch_bounds__(NTHR, 3) void win_topk_kernel(
    const float* __restrict__ mixed,    // [B, S]
    const float* __restrict__ ref,      // [A, R, S]
    const float* __restrict__ weights,  // [K]
    float* __restrict__ out,            // [6*W] scores ++ [6*W*K] idx (as float)
    int S, int W, int write_idx)
{
    const int wg   = blockIdx.x;        // window-pair index
    const int a    = blockIdx.y;
    const int tid  = threadIdx.x;
    const int warp = tid >> 5;
    const int lane = tid & 31;

    extern __shared__ __align__(16) float4 dyn[];
    float4* refbuf = dyn;                        // [NWARP][2][NV4S]
    float4* smix   = dyn + NWARP * 2 * NV4S;     // [BNUM][NV4S]
    __shared__ float sm_scores[BNUM][WPC][RNUM];
    __shared__ float sm_w[KSEL];

    const long base = (long)wg * SPAN;

    // Stage mixed span (both batch rows) into shared, vectorized.
    {
        const float4* m4 = (const float4*)mixed;  // 16B-aligned spans
        for (int i = tid; i < BNUM * NV4S; i += NTHR) {   // 400 vec4
            int b = i / NV4S, v = i % NV4S;
            smix[i] = m4[((long)b * S + base) / 4 + v];
        }
        if (tid < KSEL) sm_w[tid] = weights[tid];
    }
    __syncthreads();

    const float4* sm0 = smix;
    const float4* sm1 = smix + NV4S;

    // Register-cache this lane's mixed slice (same positions for every row).
    float4 m0r[6], m1r[6];
    #pragma unroll
    for (int j = 0; j < 6; j++) {
        m0r[j] = sm0[lane + j * 32];
        m1r[j] = sm1[lane + j * 32];
    }
    const bool tail = (lane < NV4S - 192);        // lanes 0..7
    float4 mt0 = make_float4(0.f, 0.f, 0.f, 0.f);
    float4 mt1 = make_float4(0.f, 0.f, 0.f, 0.f);
    if (tail) { mt0 = sm0[192 + lane]; mt1 = sm1[192 + lane]; }

    const float* refa = ref + ((long)a * RNUM + warp * RPW) * S + base;
    float4* rb = refbuf + warp * 2 * NV4S;

    // Issue one row's 3200B into a smem buffer (one commit group per row).
    #define ISSUE_ROW(ri, buf)                                              \
        do {                                                                \
            const float4* src_ = (const float4*)(refa + (long)(ri) * S);    \
            float4* dst_ = rb + (buf) * NV4S;                               \
            _Pragma("unroll")                                               \
            for (int j_ = 0; j_ < 6; j_++)                                  \
                cpa16(dst_ + lane + j_ * 32, src_ + lane + j_ * 32);        \
            if (tail) cpa16(dst_ + 192 + lane, src_ + 192 + lane);          \
            asm volatile("cp.async.commit_group;\n" ::: "memory");          \
        } while (0)

    ISSUE_ROW(0, 0);
    ISSUE_ROW(1, 1);

    #pragma unroll 1
    for (int i = 0; i < RPW; i++) {
        if (i < RPW - 1) asm volatile("cp.async.wait_group 1;\n" ::: "memory");
        else             asm volatile("cp.async.wait_group 0;\n" ::: "memory");

        const float4* rbuf = rb + (i & 1) * NV4S;

        float s00 = 0.f, s01 = 0.f;   // batch0: win0, win1
        float s10 = 0.f, s11 = 0.f;   // batch1: win0, win1

        #pragma unroll
        for (int j = 0; j < 6; j++) {            // 192 vec4 full-warp
            const int l = j * 32 + lane;
            float4 rv = rbuf[l];                  // same-lane produced data
            float c0 = rv.x * m0r[j].x;
            c0 = fmaf(rv.y, m0r[j].y, c0);
            c0 = fmaf(rv.z, m0r[j].z, c0);
            c0 = fmaf(rv.w, m0r[j].w, c0);
            float c1 = rv.x * m1r[j].x;
            c1 = fmaf(rv.y, m1r[j].y, c1);
            c1 = fmaf(rv.z, m1r[j].z, c1);
            c1 = fmaf(rv.w, m1r[j].w, c1);
            if (l < WIN / 4) { s00 += c0; s10 += c1; }
            else             { s01 += c0; s11 += c1; }
        }
        if (tail) {                               // local 192..199, win1
            float4 rv = rbuf[192 + lane];
            float c0 = rv.x * mt0.x;
            c0 = fmaf(rv.y, mt0.y, c0);
            c0 = fmaf(rv.z, mt0.z, c0);
            c0 = fmaf(rv.w, mt0.w, c0);
            float c1 = rv.x * mt1.x;
            c1 = fmaf(rv.y, mt1.y, c1);
            c1 = fmaf(rv.z, mt1.z, c1);
            c1 = fmaf(rv.w, mt1.w, c1);
            s01 += c0; s11 += c1;
        }

        // Refill the just-freed buffer with row i+2.
        if (i < RPW - 2) ISSUE_ROW(i + 2, i & 1);

        // Warp reductions (4 values)
        #pragma unroll
        for (int off = 16; off > 0; off >>= 1) {
            s00 += __shfl_down_sync(0xffffffffu, s00, off);
            s01 += __shfl_down_sync(0xffffffffu, s01, off);
            s10 += __shfl_down_sync(0xffffffffu, s10, off);
            s11 += __shfl_down_sync(0xffffffffu, s11, off);
        }
        if (lane == 0) {
            const int r = warp * RPW + i;
            sm_scores[0][0][r] = s00 * (1.0f / WIN);
            sm_scores[0][1][r] = s01 * (1.0f / WIN);
            sm_scores[1][0][r] = s10 * (1.0f / WIN);
            sm_scores[1][1][r] = s11 * (1.0f / WIN);
        }
    }
    __syncthreads();

    // Top-K (K=8) over 64 refs; warps 0..3 handle the 4 (b, win) combos.
    if (warp < BNUM * WPC) {
        const int b   = warp >> 1;
        const int win = warp & 1;
        float v0 = sm_scores[b][win][lane];
        float v1 = sm_scores[b][win][lane + 32];
        float acc = 0.f;

        const int  wglob = wg * WPC + win;
        const long ow    = ((long)b * ANUM + a) * W + wglob;
        const long ibase = (long)BNUM * ANUM * W + ow * KSEL;

        #pragma unroll
        for (int k = 0; k < KSEL; k++) {
            float bv; int bi;
            if (v0 >= v1) { bv = v0; bi = lane; }        // ties -> lower index
            else          { bv = v1; bi = lane + 32; }
            #pragma unroll
            for (int off = 16; off > 0; off >>= 1) {
                float ov = __shfl_xor_sync(0xffffffffu, bv, off);
                int   oi = __shfl_xor_sync(0xffffffffu, bi, off);
                if (ov > bv || (ov == bv && oi < bi)) { bv = ov; bi = oi; }
            }
            acc = fmaf(bv, sm_w[k], acc);
            if (write_idx && lane == 0) out[ibase + k] = (float)bi;
            if (bi == lane)      v0 = -CUDART_INF_F;
            if (bi == lane + 32) v1 = -CUDART_INF_F;
        }
        if (lane == 0) out[ow] = acc;
    }
}

extern "C" void kernel_launch(void* const* d_in, const int* in_sizes, int n_in,
                              void* d_out, int out_size) {
    const float* mixed   = (const float*)d_in[0];
    const float* ref     = (const float*)d_in[1];
    const float* weights = (const float*)d_in[2];
    float* out = (float*)d_out;

    const int S = in_sizes[0] / BNUM;      // 400000
    const int W = S / WIN;                 // 1000
    const int write_idx = (out_size >= BNUM * ANUM * W * (1 + KSEL)) ? 1 : 0;

    cudaFuncSetAttribute(win_topk_kernel,
                         cudaFuncAttributeMaxDynamicSharedMemorySize, DYN_BYTES);

    dim3 grid(W / WPC, ANUM);              // (500, 3) = 1500 CTAs
    win_topk_kernel<<<grid, NTHR, DYN_BYTES>>>(mixed, ref, weights, out,
                                               S, W, write_idx);
}